// round 12
// baseline (speedup 1.0000x reference)
#include <cuda_runtime.h>
#include <cuda_fp16.h>
#include <math.h>
#include <stdint.h>

#define FT 256
#define NC 16
#define NMAX 100000
#define G1 444            // 3 blocks/SM * 148 SMs (k_main)
#define MTILE 128

typedef unsigned long long ull;

// -------- device scratch (static; no allocation allowed) --------
__device__ __half g_rawH[(size_t)(NMAX + MTILE) * FT];  // row-major fp16 (+pad rows stay zero)
__device__ float  g_rnormP[(size_t)NMAX * 2];           // per-row normsq partials (2 per row)
__device__ float  g_partial[(size_t)G1 * NC * FT];      // per-block class partials
__device__ int    g_pcnt[G1 * NC];                      // per-block class counts
__device__ __half g_aveH[NC * FT];                      // pre-swizzled B image (8KB)
__device__ float  g_avenorm[NC];

__device__ __forceinline__ float eluf(float x) {
    return x > 0.f ? x : (__expf(x) - 1.f);
}
__device__ __forceinline__ ull pack2(float x, float y) {
    ull r; asm("mov.b64 %0,{%1,%2};" : "=l"(r) : "f"(x), "f"(y)); return r;
}
__device__ __forceinline__ uint32_t smem_u32(const void* p) {
    uint32_t a;
    asm("{ .reg .u64 t; cvta.to.shared.u64 t, %1; cvt.u32.u64 %0, t; }" : "=r"(a) : "l"(p));
    return a;
}

// ============ kernel 1: barrier-free pointwise, float4 datapath ============
// 8 warps = 4 teams of 2; team t processes rows 4*i+t; thread owns 4 fixed columns.
__global__ void __launch_bounds__(256, 3)
k_main(const float4* __restrict__ seq4, const float4* __restrict__ seq14,
       const int* __restrict__ labels,
       const float4* __restrict__ p14, const float4* __restrict__ p24,
       const float4* __restrict__ p34, const float* __restrict__ wwp,
       const float* __restrict__ wwf, const float4* __restrict__ wdp4,
       const float* __restrict__ a4p, int N) {
    extern __shared__ char smraw[];
    ulonglong2* s_acc = (ulonglong2*)smraw;            // [team(4)][cls(16)][c4(64)] = 64KB
    int*        s_cnt = (int*)(smraw + 65536);         // 16 ints

    int tid  = threadIdx.x;
    int lane = tid & 31;
    int warp = tid >> 5;
    int team = warp >> 1;                 // 0..3
    int tw   = warp & 1;                  // warp within team
    int c4   = tw * 32 + lane;            // float4-column 0..63 (cols 4c4..4c4+3)
    float a4 = a4p[0];
    int NP4 = N >> 2;

    #pragma unroll
    for (int i = tid; i < 4 * NC * 64; i += 256)
        s_acc[i] = make_ulonglong2(0ull, 0ull);
    if (tid < NC) s_cnt[tid] = 0;

    // coef for this thread's 4 columns
    float k0, k1, k2, k3;
    {
        float wp0 = wwp[0], wp1 = wwp[1], wp2 = wwp[2];
        float f0 = wwf[0], f1 = wwf[1];
        float4 q1 = p14[c4], q2 = p24[c4], q3 = p34[c4], qd = wdp4[c4];
        float s;
        s = wp0*q1.x + wp1*q2.x + wp2*q3.x; k0 = f0*(s > 0.f ? s+1.f : __expf(s)) + f1*qd.x;
        s = wp0*q1.y + wp1*q2.y + wp2*q3.y; k1 = f0*(s > 0.f ? s+1.f : __expf(s)) + f1*qd.y;
        s = wp0*q1.z + wp1*q2.z + wp2*q3.z; k2 = f0*(s > 0.f ? s+1.f : __expf(s)) + f1*qd.z;
        s = wp0*q1.w + wp1*q2.w + wp2*q3.w; k3 = f0*(s > 0.f ? s+1.f : __expf(s)) + f1*qd.w;
    }
    __syncthreads();

    ulonglong2* accT = s_acc + team * (NC * 64) + c4;

    #pragma unroll 2
    for (int i = blockIdx.x; i < NP4; i += G1) {
        int row = 4 * i + team;
        int lb = __ldg(labels + row);
        float4 x = seq4 [(size_t)row * 64 + c4];
        float4 y = seq14[(size_t)row * 64 + c4];
        float v0 = fmaf(a4, y.x, eluf(k0 * x.x));
        float v1 = fmaf(a4, y.y, eluf(k1 * x.y));
        float v2 = fmaf(a4, y.z, eluf(k2 * x.z));
        float v3 = fmaf(a4, y.w, eluf(k3 * x.w));

        // norm partial (this warp's 128 cols)
        float ss = fmaf(v0, v0, fmaf(v1, v1, fmaf(v2, v2, v3 * v3)));
        #pragma unroll
        for (int o = 16; o; o >>= 1) ss += __shfl_xor_sync(0xffffffffu, ss, o);
        if (lane == 0) g_rnormP[(size_t)row * 2 + tw] = ss;

        // fp16 scratch, row-major, coalesced 256B/warp
        __half2 h0 = __floats2half2_rn(v0, v1);
        __half2 h1 = __floats2half2_rn(v2, v3);
        uint2 w; w.x = *(uint32_t*)&h0; w.y = *(uint32_t*)&h1;
        *(uint2*)(g_rawH + (size_t)row * FT + 4 * c4) = w;

        // class sum: exclusive (team,c4) ulonglong2 accumulator
        ull va = pack2(v0, v1), vb = pack2(v2, v3);
        ulonglong2* a = accT + lb * 64;
        ulonglong2 old = *a;
        asm("add.rn.f32x2 %0, %0, %1;" : "+l"(old.x) : "l"(va));
        asm("add.rn.f32x2 %0, %0, %1;" : "+l"(old.y) : "l"(vb));
        *a = old;

        if (tw == 0 && lane == 0) atomicAdd(&s_cnt[lb], 1);
    }
    __syncthreads();

    // dump: merge the four team copies
    {
        ulonglong2* gp = (ulonglong2*)g_partial + (size_t)blockIdx.x * (NC * 64);
        #pragma unroll
        for (int i = tid; i < NC * 64; i += 256) {
            ulonglong2 a = s_acc[i];
            ulonglong2 b = s_acc[NC * 64 + i];
            ulonglong2 c = s_acc[2 * NC * 64 + i];
            ulonglong2 d = s_acc[3 * NC * 64 + i];
            asm("add.rn.f32x2 %0, %0, %1;" : "+l"(a.x) : "l"(b.x));
            asm("add.rn.f32x2 %0, %0, %1;" : "+l"(a.y) : "l"(b.y));
            asm("add.rn.f32x2 %0, %0, %1;" : "+l"(c.x) : "l"(d.x));
            asm("add.rn.f32x2 %0, %0, %1;" : "+l"(c.y) : "l"(d.y));
            asm("add.rn.f32x2 %0, %0, %1;" : "+l"(a.x) : "l"(c.x));
            asm("add.rn.f32x2 %0, %0, %1;" : "+l"(a.y) : "l"(c.y));
            gp[i] = a;
        }
        if (tid < NC) g_pcnt[blockIdx.x * NC + tid] = s_cnt[tid];
    }
}

// ============ kernel 2: reduce partials -> ave (fp16 B image), avenorm ============
__global__ void __launch_bounds__(1024)
k_reduce() {
    __shared__ float s_part[3 * 256];
    __shared__ float s_ave2[256];
    __shared__ float s_red[8];
    __shared__ int   s_ci[32];
    __shared__ int   s_cnt;
    int cls = blockIdx.x, tid = threadIdx.x;
    int col = tid & 255, grp = tid >> 8;

    // 4-way split partial sum (111 blocks each; 444 = 4*111), 4 accumulators
    const float* gp = g_partial + (size_t)cls * 256 + col + (size_t)(grp * 111) * 4096;
    float s0 = 0.f, s1 = 0.f, s2 = 0.f, s3 = 0.f;
    #pragma unroll 4
    for (int b = 0; b < 108; b += 4) {
        s0 += gp[(size_t)(b    ) * 4096];
        s1 += gp[(size_t)(b + 1) * 4096];
        s2 += gp[(size_t)(b + 2) * 4096];
        s3 += gp[(size_t)(b + 3) * 4096];
    }
    s0 += gp[(size_t)108 * 4096];
    s1 += gp[(size_t)109 * 4096];
    s2 += gp[(size_t)110 * 4096];
    float s = (s0 + s1) + (s2 + s3);
    if (grp) s_part[(grp - 1) * 256 + col] = s;

    // class count from per-block integer histograms
    int c = (tid < G1) ? g_pcnt[tid * NC + cls] : 0;
    #pragma unroll
    for (int o = 16; o; o >>= 1) c += __shfl_xor_sync(0xffffffffu, c, o);
    if ((tid & 31) == 0) s_ci[tid >> 5] = c;
    __syncthreads();
    if (tid == 0) {
        int t = 0;
        #pragma unroll
        for (int i = 0; i < 32; i++) t += s_ci[i];
        s_cnt = t;
    }
    __syncthreads();

    if (grp == 0) {
        float a = (s + s_part[col] + s_part[256 + col] + s_part[512 + col])
                / fmaxf((float)s_cnt, 1.f);
        __half hv = __float2half_rn(a);
        float af = __half2float(hv);
        s_ave2[col] = af * af;
        // swizzled B image: row=cls (512B rows), 16B-chunk index XOR (cls&7)
        int chunk = col >> 3;
        int off = cls * 512 + ((chunk ^ (cls & 7)) << 4) + (col & 7) * 2;
        *(__half*)((char*)g_aveH + off) = hv;
    }
    __syncthreads();

    if (tid < 256) {
        float v = s_ave2[tid];
        #pragma unroll
        for (int o = 16; o; o >>= 1) v += __shfl_xor_sync(0xffffffffu, v, o);
        if ((tid & 31) == 0) s_red[tid >> 5] = v;
    }
    __syncthreads();
    if (tid == 0) {
        float t = 0.f;
        #pragma unroll
        for (int i = 0; i < 8; i++) t += s_red[i];
        g_avenorm[cls] = sqrtf(t);
    }
}

// ============ kernel 3: HMMA GEMM + cosine + softmax; warp-per-16-rows ============
// smem: A 64KB (8 warp slices x 8KB, chunk^row swizzle) + B 8KB (pre-swizzled)
__global__ void __launch_bounds__(256)
k_out(float* __restrict__ out, int N) {
    extern __shared__ char sm[];
    uint32_t sA = smem_u32(sm);
    uint32_t sB = sA + 65536u;

    int tid  = threadIdx.x;
    int wid  = tid >> 5;
    int lane = tid & 31;
    int rowbase = blockIdx.x * MTILE + wid * 16;

    // B image: 512 chunks, 2 per thread
    {
        const char* gB = (const char*)g_aveH;
        #pragma unroll
        for (int it = 0; it < 2; it++) {
            int i = it * 256 + tid;
            asm volatile("cp.async.cg.shared.global [%0], [%1], 16;"
                         :: "r"(sB + i * 16), "l"(gB + (size_t)i * 16) : "memory");
        }
    }
    // A warp slice: 16 rows x 512B
    {
        const char* gA = (const char*)(g_rawH + (size_t)rowbase * FT);
        uint32_t aslice = sA + (uint32_t)(wid * 8192);
        #pragma unroll
        for (int it = 0; it < 16; it++) {
            uint32_t off = aslice + (uint32_t)(it * 512) + (uint32_t)((lane ^ (it & 7)) << 4);
            asm volatile("cp.async.cg.shared.global [%0], [%1], 16;"
                         :: "r"(off), "l"(gA + (size_t)it * 512 + (size_t)lane * 16) : "memory");
        }
    }
    asm volatile("cp.async.commit_group;" ::: "memory");
    asm volatile("cp.async.wait_group 0;" ::: "memory");
    __syncthreads();

    // ---- mma.sync m16n8k16: one m16 tile per warp, 2 n-tiles, 16 k-steps ----
    float c0[4] = {0,0,0,0}, c1[4] = {0,0,0,0};
    int sel   = lane >> 3;
    int lrow8 = lane & 7;
    int lrA = (sel & 1) * 8 + lrow8;     // local A row 0..15
    int cAadd = sel >> 1;
    int rB  = (sel >> 1) * 8 + lrow8;    // B row (class)
    int cBadd = sel & 1;
    uint32_t aab = sA + (uint32_t)(wid * 8192) + (uint32_t)(lrA * 512);
    uint32_t bab = sB + (uint32_t)(rB * 512);

    #pragma unroll
    for (int k = 0; k < 16; k++) {
        int cbase = 2 * k;
        uint32_t b0, b1, b2, b3;
        uint32_t baddr = bab + (uint32_t)(((cbase + cBadd) ^ (rB & 7)) << 4);
        asm volatile("ldmatrix.sync.aligned.m8n8.x4.shared.b16 {%0,%1,%2,%3}, [%4];"
                     : "=r"(b0), "=r"(b1), "=r"(b2), "=r"(b3) : "r"(baddr));
        uint32_t a0, a1, a2, a3;
        uint32_t aaddr = aab + (uint32_t)(((cbase + cAadd) ^ (lrA & 7)) << 4);
        asm volatile("ldmatrix.sync.aligned.m8n8.x4.shared.b16 {%0,%1,%2,%3}, [%4];"
                     : "=r"(a0), "=r"(a1), "=r"(a2), "=r"(a3) : "r"(aaddr));
        asm volatile("mma.sync.aligned.m16n8k16.row.col.f32.f16.f16.f32 "
                     "{%0,%1,%2,%3}, {%4,%5,%6,%7}, {%8,%9}, {%0,%1,%2,%3};"
                     : "+f"(c0[0]), "+f"(c0[1]), "+f"(c0[2]), "+f"(c0[3])
                     : "r"(a0), "r"(a1), "r"(a2), "r"(a3), "r"(b0), "r"(b1));
        asm volatile("mma.sync.aligned.m16n8k16.row.col.f32.f16.f16.f32 "
                     "{%0,%1,%2,%3}, {%4,%5,%6,%7}, {%8,%9}, {%0,%1,%2,%3};"
                     : "+f"(c1[0]), "+f"(c1[1]), "+f"(c1[2]), "+f"(c1[3])
                     : "r"(a0), "r"(a1), "r"(a2), "r"(a3), "r"(b2), "r"(b3));
    }

    // ---- epilogue: quad owns a row's 16 cols; cosine + softmax in registers ----
    int j2 = (lane & 3) * 2;
    float an0 = __ldg(&g_avenorm[j2]);
    float an1 = __ldg(&g_avenorm[j2 + 1]);
    float an2 = __ldg(&g_avenorm[j2 + 8]);
    float an3 = __ldg(&g_avenorm[j2 + 9]);

    #pragma unroll
    for (int h = 0; h < 2; h++) {
        int r = rowbase + (lane >> 2) + h * 8;
        int rc = r < N ? r : N - 1;
        float2 rp = *(const float2*)(g_rnormP + (size_t)rc * 2);
        float rn = sqrtf(rp.x + rp.y);
        float v0 = __fdividef(c0[2*h],   fmaxf(rn * an0, 1e-8f));
        float v1 = __fdividef(c0[2*h+1], fmaxf(rn * an1, 1e-8f));
        float v2 = __fdividef(c1[2*h],   fmaxf(rn * an2, 1e-8f));
        float v3 = __fdividef(c1[2*h+1], fmaxf(rn * an3, 1e-8f));
        float mx = fmaxf(fmaxf(v0, v1), fmaxf(v2, v3));
        mx = fmaxf(mx, __shfl_xor_sync(0xffffffffu, mx, 1));
        mx = fmaxf(mx, __shfl_xor_sync(0xffffffffu, mx, 2));
        v0 = __expf(v0 - mx); v1 = __expf(v1 - mx);
        v2 = __expf(v2 - mx); v3 = __expf(v3 - mx);
        float ssum = v0 + v1 + v2 + v3;
        ssum += __shfl_xor_sync(0xffffffffu, ssum, 1);
        ssum += __shfl_xor_sync(0xffffffffu, ssum, 2);
        float inv = 1.f / ssum;
        if (r < N) {
            float2* op = (float2*)(out + (size_t)r * NC);
            op[j2 >> 1]       = make_float2(v0 * inv, v1 * inv);
            op[(j2 >> 1) + 4] = make_float2(v2 * inv, v3 * inv);
        }
    }
}

// ---------------- launcher ----------------
extern "C" void kernel_launch(void* const* d_in, const int* in_sizes, int n_in,
                              void* d_out, int out_size) {
    const float* seq    = (const float*)d_in[0];
    const float* seq1   = (const float*)d_in[1];
    const int*   labels = (const int*)  d_in[2];
    const float* p1     = (const float*)d_in[3];
    const float* p2     = (const float*)d_in[4];
    const float* p3     = (const float*)d_in[5];
    const float* wwp    = (const float*)d_in[6];
    const float* wwf    = (const float*)d_in[7];
    const float* wdp    = (const float*)d_in[8];
    const float* a4     = (const float*)d_in[9];
    float* out = (float*)d_out;

    int N = in_sizes[0] / FT;
    if (N > NMAX) N = NMAX;
    int mtiles = (N + MTILE - 1) / MTILE;       // 782

    int smem1 = 65536 + 64;                     // 4 team copies + counters
    int smem3 = 65536 + 8192;                   // 72KB
    cudaFuncSetAttribute(k_main, cudaFuncAttributeMaxDynamicSharedMemorySize, smem1);
    cudaFuncSetAttribute(k_out,  cudaFuncAttributeMaxDynamicSharedMemorySize, smem3);

    k_main<<<G1, 256, smem1>>>((const float4*)seq, (const float4*)seq1, labels,
                               (const float4*)p1, (const float4*)p2, (const float4*)p3,
                               wwp, wwf, (const float4*)wdp, a4, N);
    k_reduce<<<NC, 1024>>>();
    k_out<<<mtiles, 256, smem3>>>(out, N);
}

// round 13
// speedup vs baseline: 1.2931x; 1.2931x over previous
#include <cuda_runtime.h>
#include <cuda_fp16.h>
#include <math.h>
#include <stdint.h>

#define FT 256
#define NC 16
#define NMAX 100000
#define G2 888            // 6 blocks/SM * 148 SMs
#define MTILE 128

typedef unsigned long long ull;

// -------- device scratch (static; no allocation allowed) --------
__device__ __half g_rawH[(size_t)(NMAX + MTILE) * FT];  // row-major fp16 (+pad rows stay zero)
__device__ float  g_rnormP[(size_t)NMAX * 4];           // per-row normsq partials (4 per row)
__device__ float  g_partial[(size_t)G2 * NC * FT];      // per-block class partials
__device__ int    g_pcnt[G2 * NC];                      // per-block class counts
__device__ __half g_aveH[NC * FT];                      // pre-swizzled B image (8KB)

__device__ __forceinline__ float eluf(float x) {
    return x > 0.f ? x : (__expf(x) - 1.f);
}
__device__ __forceinline__ ull pack2(float x, float y) {
    ull r; asm("mov.b64 %0,{%1,%2};" : "=l"(r) : "f"(x), "f"(y)); return r;
}
__device__ __forceinline__ uint32_t smem_u32(const void* p) {
    uint32_t a;
    asm("{ .reg .u64 t; cvta.to.shared.u64 t, %1; cvt.u32.u64 %0, t; }" : "=r"(a) : "l"(p));
    return a;
}

// ============ kernel 1: barrier-free pointwise + fp16 store + class sums ============
// (Round-11 shape: best measured. 8 warps = 2 teams of 4; thread owns 2 fixed columns.)
__global__ void __launch_bounds__(256, 6)
k_main(const float2* __restrict__ seq2, const float2* __restrict__ seq12,
       const int* __restrict__ labels,
       const float2* __restrict__ p12, const float2* __restrict__ p22,
       const float2* __restrict__ p32, const float* __restrict__ wwp,
       const float* __restrict__ wwf, const float2* __restrict__ wdp2,
       const float* __restrict__ a4p, int N) {
    __shared__ ull s_acc[2 * NC * 128];   // [team][cls][colpair] f32x2, 32KB
    __shared__ int s_cnt[NC];

    int tid  = threadIdx.x;
    int lane = tid & 31;
    int warp = tid >> 5;
    int team = warp >> 2;                 // 0/1
    int wq   = warp & 3;                  // quarter within team
    int cp   = wq * 32 + lane;            // colpair 0..127 (cols 2cp, 2cp+1)
    float a4 = a4p[0];
    int NP2 = N >> 1;

    #pragma unroll
    for (int i = tid; i < 2 * NC * 128; i += 256) s_acc[i] = 0ull;
    if (tid < NC) s_cnt[tid] = 0;

    // coef for this thread's 2 columns
    float c0, c1;
    {
        float wp0 = wwp[0], wp1 = wwp[1], wp2 = wwp[2];
        float f0 = wwf[0], f1 = wwf[1];
        float2 q1 = p12[cp], q2 = p22[cp], q3 = p32[cp], qd = wdp2[cp];
        float s0 = wp0*q1.x + wp1*q2.x + wp2*q3.x;
        float s1 = wp0*q1.y + wp1*q2.y + wp2*q3.y;
        c0 = f0 * (s0 > 0.f ? s0 + 1.f : __expf(s0)) + f1 * qd.x;
        c1 = f0 * (s1 > 0.f ? s1 + 1.f : __expf(s1)) + f1 * qd.y;
    }
    __syncthreads();

    ull* accT = s_acc + team * (NC * 128) + cp;

    #pragma unroll 2
    for (int i = blockIdx.x; i < NP2; i += G2) {
        int row = 2 * i + team;
        int lb = __ldg(labels + row);
        float2 x = seq2 [(size_t)row * 128 + cp];
        float2 y = seq12[(size_t)row * 128 + cp];
        float v0 = fmaf(a4, y.x, eluf(c0 * x.x));
        float v1 = fmaf(a4, y.y, eluf(c1 * x.y));

        // norm partial (this warp's 64 cols)
        float ss = fmaf(v0, v0, v1 * v1);
        #pragma unroll
        for (int o = 16; o; o >>= 1) ss += __shfl_xor_sync(0xffffffffu, ss, o);
        if (lane == 0) g_rnormP[(size_t)row * 4 + wq] = ss;

        // fp16 scratch, row-major, coalesced 128B/warp
        __half2 h = __floats2half2_rn(v0, v1);
        *(__half2*)(g_rawH + (size_t)row * FT + 2 * cp) = h;

        // class sum: exclusive f32x2 accumulator (team,colpair)
        ull v = pack2(v0, v1);
        ull* a = accT + lb * 128;
        ull old = *a;
        asm("add.rn.f32x2 %0, %0, %1;" : "+l"(old) : "l"(v));
        *a = old;

        if (wq == 0 && lane == 0) atomicAdd(&s_cnt[lb], 1);
    }
    __syncthreads();

    // dump: merge the two team copies
    {
        ull* gp = (ull*)g_partial + (size_t)blockIdx.x * (NC * 128);
        #pragma unroll
        for (int i = tid; i < NC * 128; i += 256) {
            ull a = s_acc[i], b = s_acc[NC * 128 + i];
            asm("add.rn.f32x2 %0, %0, %1;" : "+l"(a) : "l"(b));
            gp[i] = a;
        }
        if (tid < NC) g_pcnt[blockIdx.x * NC + tid] = s_cnt[tid];
    }
}

// ============ kernel 2: reduce partials -> ave (fp16 B image) ============
// avenorm moved to k_out => columns decouple => 64 blocks (cls, col-quarter)
__global__ void __launch_bounds__(512)
k_reduce() {
    __shared__ float s_part[7 * 64];
    __shared__ int   s_ci[16];
    __shared__ int   s_cnt;
    int bid = blockIdx.x;
    int cls = bid & 15, cq = bid >> 4;     // class, column quarter
    int tid = threadIdx.x;
    int c64 = tid & 63, grp = tid >> 6;    // 8 groups of 111 partial-blocks
    int col = cq * 64 + c64;

    const float* gp = g_partial + (size_t)cls * 256 + col + (size_t)(grp * 111) * 4096;
    float s0 = 0.f, s1 = 0.f, s2 = 0.f, s3 = 0.f;
    #pragma unroll 4
    for (int b = 0; b < 108; b += 4) {
        s0 += gp[(size_t)(b    ) * 4096];
        s1 += gp[(size_t)(b + 1) * 4096];
        s2 += gp[(size_t)(b + 2) * 4096];
        s3 += gp[(size_t)(b + 3) * 4096];
    }
    s0 += gp[(size_t)108 * 4096];
    s1 += gp[(size_t)109 * 4096];
    s2 += gp[(size_t)110 * 4096];
    float s = (s0 + s1) + (s2 + s3);
    if (grp) s_part[(grp - 1) * 64 + c64] = s;

    // class count from per-block integer histograms (888 = 512 + 376)
    int c = g_pcnt[tid * NC + cls];
    if (tid + 512 < G2) c += g_pcnt[(tid + 512) * NC + cls];
    #pragma unroll
    for (int o = 16; o; o >>= 1) c += __shfl_xor_sync(0xffffffffu, c, o);
    if ((tid & 31) == 0) s_ci[tid >> 5] = c;
    __syncthreads();
    if (tid == 0) {
        int t = 0;
        #pragma unroll
        for (int i = 0; i < 16; i++) t += s_ci[i];
        s_cnt = t;
    }
    __syncthreads();

    if (grp == 0) {
        float a = s;
        #pragma unroll
        for (int g = 0; g < 7; g++) a += s_part[g * 64 + c64];
        a /= fmaxf((float)s_cnt, 1.f);
        __half hv = __float2half_rn(a);
        // swizzled B image: row=cls (512B rows), 16B-chunk index XOR (cls&7)
        int chunk = col >> 3;
        int off = cls * 512 + ((chunk ^ (cls & 7)) << 4) + (col & 7) * 2;
        *(__half*)((char*)g_aveH + off) = hv;
    }
}

// ============ kernel 3: HMMA GEMM + cosine + softmax; warp-per-16-rows ============
// smem: A 64KB (8 warp slices x 8KB, chunk^row swizzle) + B 8KB (pre-swizzled)
// avenorm computed in-kernel from the smem B image.
__global__ void __launch_bounds__(256)
k_out(float* __restrict__ out, int N) {
    extern __shared__ char sm[];
    __shared__ float s_an[NC];
    uint32_t sA = smem_u32(sm);
    uint32_t sB = sA + 65536u;

    int tid  = threadIdx.x;
    int wid  = tid >> 5;
    int lane = tid & 31;
    int rowbase = blockIdx.x * MTILE + wid * 16;

    // B image: 512 chunks, 2 per thread
    {
        const char* gB = (const char*)g_aveH;
        #pragma unroll
        for (int it = 0; it < 2; it++) {
            int i = it * 256 + tid;
            asm volatile("cp.async.cg.shared.global [%0], [%1], 16;"
                         :: "r"(sB + i * 16), "l"(gB + (size_t)i * 16) : "memory");
        }
    }
    // A warp slice: 16 rows x 512B
    {
        const char* gA = (const char*)(g_rawH + (size_t)rowbase * FT);
        uint32_t aslice = sA + (uint32_t)(wid * 8192);
        #pragma unroll
        for (int it = 0; it < 16; it++) {
            uint32_t off = aslice + (uint32_t)(it * 512) + (uint32_t)((lane ^ (it & 7)) << 4);
            asm volatile("cp.async.cg.shared.global [%0], [%1], 16;"
                         :: "r"(off), "l"(gA + (size_t)it * 512 + (size_t)lane * 16) : "memory");
        }
    }
    asm volatile("cp.async.commit_group;" ::: "memory");
    asm volatile("cp.async.wait_group 0;" ::: "memory");
    __syncthreads();

    // ---- avenorm from smem B image: thread (cls=tid>>4, seg=tid&15) sums 16 halfs ----
    {
        int cls = tid >> 4, seg = tid & 15;
        const char* bgen = sm + 65536 + cls * 512;
        float nsq = 0.f;
        #pragma unroll
        for (int cc = 0; cc < 2; cc++) {
            int chunk = seg * 2 + cc;
            uint4 q = *(const uint4*)(bgen + ((chunk ^ (cls & 7)) << 4));
            float2 f;
            f = __half22float2(*(__half2*)&q.x); nsq = fmaf(f.x, f.x, fmaf(f.y, f.y, nsq));
            f = __half22float2(*(__half2*)&q.y); nsq = fmaf(f.x, f.x, fmaf(f.y, f.y, nsq));
            f = __half22float2(*(__half2*)&q.z); nsq = fmaf(f.x, f.x, fmaf(f.y, f.y, nsq));
            f = __half22float2(*(__half2*)&q.w); nsq = fmaf(f.x, f.x, fmaf(f.y, f.y, nsq));
        }
        #pragma unroll
        for (int o = 8; o; o >>= 1) nsq += __shfl_xor_sync(0xffffffffu, nsq, o);
        if (seg == 0) s_an[cls] = sqrtf(nsq);
    }
    __syncthreads();

    // ---- mma.sync m16n8k16: one m16 tile per warp, 2 n-tiles, 16 k-steps ----
    float c0[4] = {0,0,0,0}, c1[4] = {0,0,0,0};
    int sel   = lane >> 3;
    int lrow8 = lane & 7;
    int lrA = (sel & 1) * 8 + lrow8;     // local A row 0..15
    int cAadd = sel >> 1;
    int rB  = (sel >> 1) * 8 + lrow8;    // B row (class)
    int cBadd = sel & 1;
    uint32_t aab = sA + (uint32_t)(wid * 8192) + (uint32_t)(lrA * 512);
    uint32_t bab = sB + (uint32_t)(rB * 512);

    #pragma unroll
    for (int k = 0; k < 16; k++) {
        int cbase = 2 * k;
        uint32_t b0, b1, b2, b3;
        uint32_t baddr = bab + (uint32_t)(((cbase + cBadd) ^ (rB & 7)) << 4);
        asm volatile("ldmatrix.sync.aligned.m8n8.x4.shared.b16 {%0,%1,%2,%3}, [%4];"
                     : "=r"(b0), "=r"(b1), "=r"(b2), "=r"(b3) : "r"(baddr));
        uint32_t a0, a1, a2, a3;
        uint32_t aaddr = aab + (uint32_t)(((cbase + cAadd) ^ (lrA & 7)) << 4);
        asm volatile("ldmatrix.sync.aligned.m8n8.x4.shared.b16 {%0,%1,%2,%3}, [%4];"
                     : "=r"(a0), "=r"(a1), "=r"(a2), "=r"(a3) : "r"(aaddr));
        asm volatile("mma.sync.aligned.m16n8k16.row.col.f32.f16.f16.f32 "
                     "{%0,%1,%2,%3}, {%4,%5,%6,%7}, {%8,%9}, {%0,%1,%2,%3};"
                     : "+f"(c0[0]), "+f"(c0[1]), "+f"(c0[2]), "+f"(c0[3])
                     : "r"(a0), "r"(a1), "r"(a2), "r"(a3), "r"(b0), "r"(b1));
        asm volatile("mma.sync.aligned.m16n8k16.row.col.f32.f16.f16.f32 "
                     "{%0,%1,%2,%3}, {%4,%5,%6,%7}, {%8,%9}, {%0,%1,%2,%3};"
                     : "+f"(c1[0]), "+f"(c1[1]), "+f"(c1[2]), "+f"(c1[3])
                     : "r"(a0), "r"(a1), "r"(a2), "r"(a3), "r"(b2), "r"(b3));
    }

    // ---- epilogue: quad owns a row's 16 cols; cosine + softmax in registers ----
    int j2 = (lane & 3) * 2;
    float an0 = s_an[j2];
    float an1 = s_an[j2 + 1];
    float an2 = s_an[j2 + 8];
    float an3 = s_an[j2 + 9];

    #pragma unroll
    for (int h = 0; h < 2; h++) {
        int r = rowbase + (lane >> 2) + h * 8;
        int rc = r < N ? r : N - 1;
        float4 rp = *(const float4*)(g_rnormP + (size_t)rc * 4);
        float rn = sqrtf((rp.x + rp.y) + (rp.z + rp.w));
        float v0 = __fdividef(c0[2*h],   fmaxf(rn * an0, 1e-8f));
        float v1 = __fdividef(c0[2*h+1], fmaxf(rn * an1, 1e-8f));
        float v2 = __fdividef(c1[2*h],   fmaxf(rn * an2, 1e-8f));
        float v3 = __fdividef(c1[2*h+1], fmaxf(rn * an3, 1e-8f));
        float mx = fmaxf(fmaxf(v0, v1), fmaxf(v2, v3));
        mx = fmaxf(mx, __shfl_xor_sync(0xffffffffu, mx, 1));
        mx = fmaxf(mx, __shfl_xor_sync(0xffffffffu, mx, 2));
        v0 = __expf(v0 - mx); v1 = __expf(v1 - mx);
        v2 = __expf(v2 - mx); v3 = __expf(v3 - mx);
        float ssum = v0 + v1 + v2 + v3;
        ssum += __shfl_xor_sync(0xffffffffu, ssum, 1);
        ssum += __shfl_xor_sync(0xffffffffu, ssum, 2);
        float inv = 1.f / ssum;
        if (r < N) {
            float2* op = (float2*)(out + (size_t)r * NC);
            op[j2 >> 1]       = make_float2(v0 * inv, v1 * inv);
            op[(j2 >> 1) + 4] = make_float2(v2 * inv, v3 * inv);
        }
    }
}

// ---------------- launcher ----------------
extern "C" void kernel_launch(void* const* d_in, const int* in_sizes, int n_in,
                              void* d_out, int out_size) {
    const float* seq    = (const float*)d_in[0];
    const float* seq1   = (const float*)d_in[1];
    const int*   labels = (const int*)  d_in[2];
    const float* p1     = (const float*)d_in[3];
    const float* p2     = (const float*)d_in[4];
    const float* p3     = (const float*)d_in[5];
    const float* wwp    = (const float*)d_in[6];
    const float* wwf    = (const float*)d_in[7];
    const float* wdp    = (const float*)d_in[8];
    const float* a4     = (const float*)d_in[9];
    float* out = (float*)d_out;

    int N = in_sizes[0] / FT;
    if (N > NMAX) N = NMAX;
    int mtiles = (N + MTILE - 1) / MTILE;       // 782

    int smem3 = 65536 + 8192;                   // 72KB
    cudaFuncSetAttribute(k_out, cudaFuncAttributeMaxDynamicSharedMemorySize, smem3);

    k_main<<<G2, 256>>>((const float2*)seq, (const float2*)seq1, labels,
                        (const float2*)p1, (const float2*)p2, (const float2*)p3,
                        wwp, wwf, (const float2*)wdp, a4, N);
    k_reduce<<<64, 512>>>();
    k_out<<<mtiles, 256, smem3>>>(out, N);
}

// round 15
// speedup vs baseline: 1.3319x; 1.0300x over previous
#include <cuda_runtime.h>
#include <cuda_fp16.h>
#include <math.h>
#include <stdint.h>

#define FT 256
#define NC 16
#define NMAX 100000
#define G2 888            // 6 blocks/SM * 148 SMs
#define MTILE 128

typedef unsigned long long ull;

// -------- device scratch (static; no allocation allowed) --------
__device__ __half g_rawH[(size_t)(NMAX + MTILE) * FT];  // row-major fp16 (+pad rows stay zero)
__device__ float  g_partial[(size_t)G2 * NC * FT];      // per-block class partials
__device__ int    g_pcnt[G2 * NC];                      // per-block class counts
__device__ __half g_aveH[NC * FT];                      // pre-swizzled B image (8KB)

__device__ __forceinline__ float eluf(float x) {
    return x > 0.f ? x : (__expf(x) - 1.f);
}
__device__ __forceinline__ ull pack2(float x, float y) {
    ull r; asm("mov.b64 %0,{%1,%2};" : "=l"(r) : "f"(x), "f"(y)); return r;
}
__device__ __forceinline__ uint32_t smem_u32(const void* p) {
    uint32_t a;
    asm("{ .reg .u64 t; cvta.to.shared.u64 t, %1; cvt.u32.u64 %0, t; }" : "=r"(a) : "l"(p));
    return a;
}

// ============ kernel 1: barrier-free pointwise + fp16 store + class sums ============
// 8 warps = 2 teams of 4; team t processes rows 2*i+t; thread owns 2 fixed columns.
// Row norms are NOT computed here (k_out derives them from the fp16 scratch).
__global__ void __launch_bounds__(256, 6)
k_main(const float2* __restrict__ seq2, const float2* __restrict__ seq12,
       const int* __restrict__ labels,
       const float2* __restrict__ p12, const float2* __restrict__ p22,
       const float2* __restrict__ p32, const float* __restrict__ wwp,
       const float* __restrict__ wwf, const float2* __restrict__ wdp2,
       const float* __restrict__ a4p, int N) {
    __shared__ ull s_acc[2 * NC * 128];   // [team][cls][colpair] f32x2, 32KB
    __shared__ int s_cnt[NC];

    int tid  = threadIdx.x;
    int lane = tid & 31;
    int warp = tid >> 5;
    int team = warp >> 2;                 // 0/1
    int wq   = warp & 3;                  // quarter within team
    int cp   = wq * 32 + lane;            // colpair 0..127 (cols 2cp, 2cp+1)
    float a4 = a4p[0];
    int NP2 = N >> 1;

    #pragma unroll
    for (int i = tid; i < 2 * NC * 128; i += 256) s_acc[i] = 0ull;
    if (tid < NC) s_cnt[tid] = 0;

    // coef for this thread's 2 columns
    float c0, c1;
    {
        float wp0 = wwp[0], wp1 = wwp[1], wp2 = wwp[2];
        float f0 = wwf[0], f1 = wwf[1];
        float2 q1 = p12[cp], q2 = p22[cp], q3 = p32[cp], qd = wdp2[cp];
        float s0 = wp0*q1.x + wp1*q2.x + wp2*q3.x;
        float s1 = wp0*q1.y + wp1*q2.y + wp2*q3.y;
        c0 = f0 * (s0 > 0.f ? s0 + 1.f : __expf(s0)) + f1 * qd.x;
        c1 = f0 * (s1 > 0.f ? s1 + 1.f : __expf(s1)) + f1 * qd.y;
    }
    __syncthreads();

    ull* accT = s_acc + team * (NC * 128) + cp;

    #pragma unroll 4
    for (int i = blockIdx.x; i < NP2; i += G2) {
        int row = 2 * i + team;
        int lb = __ldg(labels + row);
        float2 x = seq2 [(size_t)row * 128 + cp];
        float2 y = seq12[(size_t)row * 128 + cp];
        float v0 = fmaf(a4, y.x, eluf(c0 * x.x));
        float v1 = fmaf(a4, y.y, eluf(c1 * x.y));

        // fp16 scratch, row-major, coalesced 128B/warp
        __half2 h = __floats2half2_rn(v0, v1);
        *(__half2*)(g_rawH + (size_t)row * FT + 2 * cp) = h;

        // class sum: exclusive f32x2 accumulator (team,colpair)
        ull v = pack2(v0, v1);
        ull* a = accT + lb * 128;
        ull old = *a;
        asm("add.rn.f32x2 %0, %0, %1;" : "+l"(old) : "l"(v));
        *a = old;

        if (wq == 0 && lane == 0) atomicAdd(&s_cnt[lb], 1);
    }
    __syncthreads();

    // dump: merge the two team copies
    {
        ull* gp = (ull*)g_partial + (size_t)blockIdx.x * (NC * 128);
        #pragma unroll
        for (int i = tid; i < NC * 128; i += 256) {
            ull a = s_acc[i], b = s_acc[NC * 128 + i];
            asm("add.rn.f32x2 %0, %0, %1;" : "+l"(a) : "l"(b));
            gp[i] = a;
        }
        if (tid < NC) g_pcnt[blockIdx.x * NC + tid] = s_cnt[tid];
    }
}

// ============ kernel 2: reduce partials -> ave (fp16 B image) ============
// columns decoupled => 64 blocks (cls, col-quarter)
__global__ void __launch_bounds__(512)
k_reduce() {
    __shared__ float s_part[7 * 64];
    __shared__ int   s_ci[16];
    __shared__ int   s_cnt;
    int bid = blockIdx.x;
    int cls = bid & 15, cq = bid >> 4;     // class, column quarter
    int tid = threadIdx.x;
    int c64 = tid & 63, grp = tid >> 6;    // 8 groups of 111 partial-blocks
    int col = cq * 64 + c64;

    const float* gp = g_partial + (size_t)cls * 256 + col + (size_t)(grp * 111) * 4096;
    float s0 = 0.f, s1 = 0.f, s2 = 0.f, s3 = 0.f;
    #pragma unroll 4
    for (int b = 0; b < 108; b += 4) {
        s0 += gp[(size_t)(b    ) * 4096];
        s1 += gp[(size_t)(b + 1) * 4096];
        s2 += gp[(size_t)(b + 2) * 4096];
        s3 += gp[(size_t)(b + 3) * 4096];
    }
    s0 += gp[(size_t)108 * 4096];
    s1 += gp[(size_t)109 * 4096];
    s2 += gp[(size_t)110 * 4096];
    float s = (s0 + s1) + (s2 + s3);
    if (grp) s_part[(grp - 1) * 64 + c64] = s;

    // class count from per-block integer histograms (888 = 512 + 376)
    int c = g_pcnt[tid * NC + cls];
    if (tid + 512 < G2) c += g_pcnt[(tid + 512) * NC + cls];
    #pragma unroll
    for (int o = 16; o; o >>= 1) c += __shfl_xor_sync(0xffffffffu, c, o);
    if ((tid & 31) == 0) s_ci[tid >> 5] = c;
    __syncthreads();
    if (tid == 0) {
        int t = 0;
        #pragma unroll
        for (int i = 0; i < 16; i++) t += s_ci[i];
        s_cnt = t;
    }
    __syncthreads();

    if (grp == 0) {
        float a = s;
        #pragma unroll
        for (int g = 0; g < 7; g++) a += s_part[g * 64 + c64];
        a /= fmaxf((float)s_cnt, 1.f);
        __half hv = __float2half_rn(a);
        // swizzled B image: row=cls (512B rows), 16B-chunk index XOR (cls&7)
        int chunk = col >> 3;
        int off = cls * 512 + ((chunk ^ (cls & 7)) << 4) + (col & 7) * 2;
        *(__half*)((char*)g_aveH + off) = hv;
    }
}

// ============ kernel 3: HMMA GEMM + row norms + cosine + softmax ============
// smem: A 64KB (8 warp slices x 8KB, chunk^row swizzle) + B 8KB (pre-swizzled)
__global__ void __launch_bounds__(256)
k_out(float* __restrict__ out, int N) {
    extern __shared__ char sm[];
    __shared__ float s_an[NC];
    __shared__ float s_rn[8][16];
    uint32_t sA = smem_u32(sm);
    uint32_t sB = sA + 65536u;

    int tid  = threadIdx.x;
    int wid  = tid >> 5;
    int lane = tid & 31;
    int rowbase = blockIdx.x * MTILE + wid * 16;

    // B image: 512 chunks, 2 per thread
    {
        const char* gB = (const char*)g_aveH;
        #pragma unroll
        for (int it = 0; it < 2; it++) {
            int i = it * 256 + tid;
            asm volatile("cp.async.cg.shared.global [%0], [%1], 16;"
                         :: "r"(sB + i * 16), "l"(gB + (size_t)i * 16) : "memory");
        }
    }
    // A warp slice: 16 rows x 512B (32 chunks/row), chunk^(row&7) swizzle
    {
        const char* gA = (const char*)(g_rawH + (size_t)rowbase * FT);
        uint32_t aslice = sA + (uint32_t)(wid * 8192);
        #pragma unroll
        for (int it = 0; it < 16; it++) {
            uint32_t off = aslice + (uint32_t)(it * 512) + (uint32_t)((lane ^ (it & 7)) << 4);
            asm volatile("cp.async.cg.shared.global [%0], [%1], 16;"
                         :: "r"(off), "l"(gA + (size_t)it * 512 + (size_t)lane * 16) : "memory");
        }
    }
    asm volatile("cp.async.commit_group;" ::: "memory");
    asm volatile("cp.async.wait_group 0;" ::: "memory");
    __syncthreads();

    // ---- avenorm from smem B image (warps 0-3): 8 lanes/class x 4 chunks = 32 ----
    if (wid < 4) {
        int t = tid;                      // 0..127
        int cls = t >> 3, seg = t & 7;
        const char* bgen = sm + 65536 + cls * 512;
        int chunk = seg * 4;
        float nsq = 0.f;
        #pragma unroll
        for (int cc = 0; cc < 4; cc++) {
            uint4 q = *(const uint4*)(bgen + (((chunk + cc) ^ (cls & 7)) << 4));
            float2 f;
            f = __half22float2(*(__half2*)&q.x); nsq = fmaf(f.x, f.x, fmaf(f.y, f.y, nsq));
            f = __half22float2(*(__half2*)&q.y); nsq = fmaf(f.x, f.x, fmaf(f.y, f.y, nsq));
            f = __half22float2(*(__half2*)&q.z); nsq = fmaf(f.x, f.x, fmaf(f.y, f.y, nsq));
            f = __half22float2(*(__half2*)&q.w); nsq = fmaf(f.x, f.x, fmaf(f.y, f.y, nsq));
        }
        #pragma unroll
        for (int o = 4; o; o >>= 1) nsq += __shfl_xor_sync(0xffffffffu, nsq, o);
        if (seg == 0) s_an[cls] = sqrtf(nsq);
    }

    // ---- row norms from this warp's A slice: 2 lanes/row x 16 chunks = 32 ----
    {
        int lrow = lane >> 1, half = lane & 1;
        const char* agen = sm + wid * 8192 + lrow * 512;
        float nsq = 0.f;
        #pragma unroll
        for (int j = 0; j < 16; j++) {
            int chunk = half * 16 + j;
            uint4 q = *(const uint4*)(agen + ((chunk ^ (lrow & 7)) << 4));
            float2 f;
            f = __half22float2(*(__half2*)&q.x); nsq = fmaf(f.x, f.x, fmaf(f.y, f.y, nsq));
            f = __half22float2(*(__half2*)&q.y); nsq = fmaf(f.x, f.x, fmaf(f.y, f.y, nsq));
            f = __half22float2(*(__half2*)&q.z); nsq = fmaf(f.x, f.x, fmaf(f.y, f.y, nsq));
            f = __half22float2(*(__half2*)&q.w); nsq = fmaf(f.x, f.x, fmaf(f.y, f.y, nsq));
        }
        nsq += __shfl_xor_sync(0xffffffffu, nsq, 1);
        if (half == 0) s_rn[wid][lrow] = sqrtf(nsq);
    }
    __syncthreads();

    // ---- mma.sync m16n8k16: one m16 tile per warp, 2 n-tiles, 16 k-steps ----
    float c0[4] = {0,0,0,0}, c1[4] = {0,0,0,0};
    int sel   = lane >> 3;
    int lrow8 = lane & 7;
    int lrA = (sel & 1) * 8 + lrow8;     // local A row 0..15
    int cAadd = sel >> 1;
    int rB  = (sel >> 1) * 8 + lrow8;    // B row (class)
    int cBadd = sel & 1;
    uint32_t aab = sA + (uint32_t)(wid * 8192) + (uint32_t)(lrA * 512);
    uint32_t bab = sB + (uint32_t)(rB * 512);

    #pragma unroll
    for (int k = 0; k < 16; k++) {
        int cbase = 2 * k;
        uint32_t b0, b1, b2, b3;
        uint32_t baddr = bab + (uint32_t)(((cbase + cBadd) ^ (rB & 7)) << 4);
        asm volatile("ldmatrix.sync.aligned.m8n8.x4.shared.b16 {%0,%1,%2,%3}, [%4];"
                     : "=r"(b0), "=r"(b1), "=r"(b2), "=r"(b3) : "r"(baddr));
        uint32_t a0, a1, a2, a3;
        uint32_t aaddr = aab + (uint32_t)(((cbase + cAadd) ^ (lrA & 7)) << 4);
        asm volatile("ldmatrix.sync.aligned.m8n8.x4.shared.b16 {%0,%1,%2,%3}, [%4];"
                     : "=r"(a0), "=r"(a1), "=r"(a2), "=r"(a3) : "r"(aaddr));
        asm volatile("mma.sync.aligned.m16n8k16.row.col.f32.f16.f16.f32 "
                     "{%0,%1,%2,%3}, {%4,%5,%6,%7}, {%8,%9}, {%0,%1,%2,%3};"
                     : "+f"(c0[0]), "+f"(c0[1]), "+f"(c0[2]), "+f"(c0[3])
                     : "r"(a0), "r"(a1), "r"(a2), "r"(a3), "r"(b0), "r"(b1));
        asm volatile("mma.sync.aligned.m16n8k16.row.col.f32.f16.f16.f32 "
                     "{%0,%1,%2,%3}, {%4,%5,%6,%7}, {%8,%9}, {%0,%1,%2,%3};"
                     : "+f"(c1[0]), "+f"(c1[1]), "+f"(c1[2]), "+f"(c1[3])
                     : "r"(a0), "r"(a1), "r"(a2), "r"(a3), "r"(b2), "r"(b3));
    }

    // ---- epilogue: quad owns a row's 16 cols; cosine + softmax in registers ----
    int j2 = (lane & 3) * 2;
    float an0 = s_an[j2];
    float an1 = s_an[j2 + 1];
    float an2 = s_an[j2 + 8];
    float an3 = s_an[j2 + 9];

    #pragma unroll
    for (int h = 0; h < 2; h++) {
        int lr = (lane >> 2) + h * 8;
        int r = rowbase + lr;
        float rn = s_rn[wid][lr];
        float v0 = __fdividef(c0[2*h],   fmaxf(rn * an0, 1e-8f));
        float v1 = __fdividef(c0[2*h+1], fmaxf(rn * an1, 1e-8f));
        float v2 = __fdividef(c1[2*h],   fmaxf(rn * an2, 1e-8f));
        float v3 = __fdividef(c1[2*h+1], fmaxf(rn * an3, 1e-8f));
        float mx = fmaxf(fmaxf(v0, v1), fmaxf(v2, v3));
        mx = fmaxf(mx, __shfl_xor_sync(0xffffffffu, mx, 1));
        mx = fmaxf(mx, __shfl_xor_sync(0xffffffffu, mx, 2));
        v0 = __expf(v0 - mx); v1 = __expf(v1 - mx);
        v2 = __expf(v2 - mx); v3 = __expf(v3 - mx);
        float ssum = v0 + v1 + v2 + v3;
        ssum += __shfl_xor_sync(0xffffffffu, ssum, 1);
        ssum += __shfl_xor_sync(0xffffffffu, ssum, 2);
        float inv = 1.f / ssum;
        if (r < N) {
            float2* op = (float2*)(out + (size_t)r * NC);
            op[j2 >> 1]       = make_float2(v0 * inv, v1 * inv);
            op[(j2 >> 1) + 4] = make_float2(v2 * inv, v3 * inv);
        }
    }
}

// ---------------- launcher ----------------
extern "C" void kernel_launch(void* const* d_in, const int* in_sizes, int n_in,
                              void* d_out, int out_size) {
    const float* seq    = (const float*)d_in[0];
    const float* seq1   = (const float*)d_in[1];
    const int*   labels = (const int*)  d_in[2];
    const float* p1     = (const float*)d_in[3];
    const float* p2     = (const float*)d_in[4];
    const float* p3     = (const float*)d_in[5];
    const float* wwp    = (const float*)d_in[6];
    const float* wwf    = (const float*)d_in[7];
    const float* wdp    = (const float*)d_in[8];
    const float* a4     = (const float*)d_in[9];
    float* out = (float*)d_out;

    int N = in_sizes[0] / FT;
    if (N > NMAX) N = NMAX;
    int mtiles = (N + MTILE - 1) / MTILE;       // 782

    int smem3 = 65536 + 8192;                   // 72KB
    cudaFuncSetAttribute(k_out, cudaFuncAttributeMaxDynamicSharedMemorySize, smem3);

    k_main<<<G2, 256>>>((const float2*)seq, (const float2*)seq1, labels,
                        (const float2*)p1, (const float2*)p2, (const float2*)p3,
                        wwp, wwf, (const float2*)wdp, a4, N);
    k_reduce<<<64, 512>>>();
    k_out<<<mtiles, 256, smem3>>>(out, N);
}

// round 16
// speedup vs baseline: 1.3335x; 1.0012x over previous
#include <cuda_runtime.h>
#include <cuda_fp16.h>
#include <math.h>
#include <stdint.h>

#define FT 256
#define NC 16
#define NMAX 100000
#define G2 888            // 6 blocks/SM * 148 SMs
#define MTILE 64

typedef unsigned long long ull;

// -------- device scratch (static; no allocation allowed) --------
__device__ __half g_rawH[(size_t)(NMAX + MTILE) * FT];  // row-major fp16 (+pad rows stay zero)
__device__ float  g_partial[(size_t)G2 * NC * FT];      // per-block class partials
__device__ int    g_pcnt[G2 * NC];                      // per-block class counts
__device__ __half g_aveH[NC * FT];                      // pre-swizzled B image (8KB)

__device__ __forceinline__ float eluf(float x) {
    return x > 0.f ? x : (__expf(x) - 1.f);
}
__device__ __forceinline__ ull pack2(float x, float y) {
    ull r; asm("mov.b64 %0,{%1,%2};" : "=l"(r) : "f"(x), "f"(y)); return r;
}
__device__ __forceinline__ uint32_t smem_u32(const void* p) {
    uint32_t a;
    asm("{ .reg .u64 t; cvta.to.shared.u64 t, %1; cvt.u32.u64 %0, t; }" : "=r"(a) : "l"(p));
    return a;
}

// ============ kernel 1: barrier-free pointwise + fp16 store + class sums ============
// (unchanged from Round 15 — best measured)
__global__ void __launch_bounds__(256, 6)
k_main(const float2* __restrict__ seq2, const float2* __restrict__ seq12,
       const int* __restrict__ labels,
       const float2* __restrict__ p12, const float2* __restrict__ p22,
       const float2* __restrict__ p32, const float* __restrict__ wwp,
       const float* __restrict__ wwf, const float2* __restrict__ wdp2,
       const float* __restrict__ a4p, int N) {
    __shared__ ull s_acc[2 * NC * 128];   // [team][cls][colpair] f32x2, 32KB
    __shared__ int s_cnt[NC];

    int tid  = threadIdx.x;
    int lane = tid & 31;
    int warp = tid >> 5;
    int team = warp >> 2;                 // 0/1
    int wq   = warp & 3;                  // quarter within team
    int cp   = wq * 32 + lane;            // colpair 0..127 (cols 2cp, 2cp+1)
    float a4 = a4p[0];
    int NP2 = N >> 1;

    #pragma unroll
    for (int i = tid; i < 2 * NC * 128; i += 256) s_acc[i] = 0ull;
    if (tid < NC) s_cnt[tid] = 0;

    // coef for this thread's 2 columns
    float c0, c1;
    {
        float wp0 = wwp[0], wp1 = wwp[1], wp2 = wwp[2];
        float f0 = wwf[0], f1 = wwf[1];
        float2 q1 = p12[cp], q2 = p22[cp], q3 = p32[cp], qd = wdp2[cp];
        float s0 = wp0*q1.x + wp1*q2.x + wp2*q3.x;
        float s1 = wp0*q1.y + wp1*q2.y + wp2*q3.y;
        c0 = f0 * (s0 > 0.f ? s0 + 1.f : __expf(s0)) + f1 * qd.x;
        c1 = f0 * (s1 > 0.f ? s1 + 1.f : __expf(s1)) + f1 * qd.y;
    }
    __syncthreads();

    ull* accT = s_acc + team * (NC * 128) + cp;

    #pragma unroll 4
    for (int i = blockIdx.x; i < NP2; i += G2) {
        int row = 2 * i + team;
        int lb = __ldg(labels + row);
        float2 x = seq2 [(size_t)row * 128 + cp];
        float2 y = seq12[(size_t)row * 128 + cp];
        float v0 = fmaf(a4, y.x, eluf(c0 * x.x));
        float v1 = fmaf(a4, y.y, eluf(c1 * x.y));

        __half2 h = __floats2half2_rn(v0, v1);
        *(__half2*)(g_rawH + (size_t)row * FT + 2 * cp) = h;

        ull v = pack2(v0, v1);
        ull* a = accT + lb * 128;
        ull old = *a;
        asm("add.rn.f32x2 %0, %0, %1;" : "+l"(old) : "l"(v));
        *a = old;

        if (wq == 0 && lane == 0) atomicAdd(&s_cnt[lb], 1);
    }
    __syncthreads();

    {
        ull* gp = (ull*)g_partial + (size_t)blockIdx.x * (NC * 128);
        #pragma unroll
        for (int i = tid; i < NC * 128; i += 256) {
            ull a = s_acc[i], b = s_acc[NC * 128 + i];
            asm("add.rn.f32x2 %0, %0, %1;" : "+l"(a) : "l"(b));
            gp[i] = a;
        }
        if (tid < NC) g_pcnt[blockIdx.x * NC + tid] = s_cnt[tid];
    }
}

// ============ kernel 2: reduce partials -> ave (fp16 B image) ============
__global__ void __launch_bounds__(512)
k_reduce() {
    __shared__ float s_part[7 * 64];
    __shared__ int   s_ci[16];
    __shared__ int   s_cnt;
    int bid = blockIdx.x;
    int cls = bid & 15, cq = bid >> 4;
    int tid = threadIdx.x;
    int c64 = tid & 63, grp = tid >> 6;
    int col = cq * 64 + c64;

    const float* gp = g_partial + (size_t)cls * 256 + col + (size_t)(grp * 111) * 4096;
    float s0 = 0.f, s1 = 0.f, s2 = 0.f, s3 = 0.f;
    #pragma unroll 4
    for (int b = 0; b < 108; b += 4) {
        s0 += gp[(size_t)(b    ) * 4096];
        s1 += gp[(size_t)(b + 1) * 4096];
        s2 += gp[(size_t)(b + 2) * 4096];
        s3 += gp[(size_t)(b + 3) * 4096];
    }
    s0 += gp[(size_t)108 * 4096];
    s1 += gp[(size_t)109 * 4096];
    s2 += gp[(size_t)110 * 4096];
    float s = (s0 + s1) + (s2 + s3);
    if (grp) s_part[(grp - 1) * 64 + c64] = s;

    int c = g_pcnt[tid * NC + cls];
    if (tid + 512 < G2) c += g_pcnt[(tid + 512) * NC + cls];
    #pragma unroll
    for (int o = 16; o; o >>= 1) c += __shfl_xor_sync(0xffffffffu, c, o);
    if ((tid & 31) == 0) s_ci[tid >> 5] = c;
    __syncthreads();
    if (tid == 0) {
        int t = 0;
        #pragma unroll
        for (int i = 0; i < 16; i++) t += s_ci[i];
        s_cnt = t;
    }
    __syncthreads();

    if (grp == 0) {
        float a = s;
        #pragma unroll
        for (int g = 0; g < 7; g++) a += s_part[g * 64 + c64];
        a /= fmaxf((float)s_cnt, 1.f);
        __half hv = __float2half_rn(a);
        int chunk = col >> 3;
        int off = cls * 512 + ((chunk ^ (cls & 7)) << 4) + (col & 7) * 2;
        *(__half*)((char*)g_aveH + off) = hv;
    }
}

// ============ kernel 3: HMMA GEMM + row norms + cosine + softmax ============
// MTILE=64, 128 threads = 4 warps x 16 rows; smem A 32KB + B 8KB => 5 blocks/SM
__global__ void __launch_bounds__(128)
k_out(float* __restrict__ out, int N) {
    extern __shared__ char sm[];
    __shared__ float s_an[NC];
    __shared__ float s_rn[4][16];
    uint32_t sA = smem_u32(sm);
    uint32_t sB = sA + 32768u;

    int tid  = threadIdx.x;
    int wid  = tid >> 5;
    int lane = tid & 31;
    int rowbase = blockIdx.x * MTILE + wid * 16;

    // B image: 512 chunks, 4 per thread
    {
        const char* gB = (const char*)g_aveH;
        #pragma unroll
        for (int it = 0; it < 4; it++) {
            int i = it * 128 + tid;
            asm volatile("cp.async.cg.shared.global [%0], [%1], 16;"
                         :: "r"(sB + i * 16), "l"(gB + (size_t)i * 16) : "memory");
        }
    }
    // A warp slice: 16 rows x 512B (32 chunks/row), chunk^(row&7) swizzle
    {
        const char* gA = (const char*)(g_rawH + (size_t)rowbase * FT);
        uint32_t aslice = sA + (uint32_t)(wid * 8192);
        #pragma unroll
        for (int it = 0; it < 16; it++) {
            uint32_t off = aslice + (uint32_t)(it * 512) + (uint32_t)((lane ^ (it & 7)) << 4);
            asm volatile("cp.async.cg.shared.global [%0], [%1], 16;"
                         :: "r"(off), "l"(gA + (size_t)it * 512 + (size_t)lane * 16) : "memory");
        }
    }
    asm volatile("cp.async.commit_group;" ::: "memory");
    asm volatile("cp.async.wait_group 0;" ::: "memory");
    __syncthreads();

    // ---- avenorm from smem B image (warps 0-1): 4 lanes/class x 8 chunks = 32 ----
    if (wid < 2) {
        int t = tid;                      // 0..63
        int cls = t >> 2, seg = t & 3;
        const char* bgen = sm + 32768 + cls * 512;
        int chunk = seg * 8;
        float nsq = 0.f;
        #pragma unroll
        for (int cc = 0; cc < 8; cc++) {
            uint4 q = *(const uint4*)(bgen + (((chunk + cc) ^ (cls & 7)) << 4));
            float2 f;
            f = __half22float2(*(__half2*)&q.x); nsq = fmaf(f.x, f.x, fmaf(f.y, f.y, nsq));
            f = __half22float2(*(__half2*)&q.y); nsq = fmaf(f.x, f.x, fmaf(f.y, f.y, nsq));
            f = __half22float2(*(__half2*)&q.z); nsq = fmaf(f.x, f.x, fmaf(f.y, f.y, nsq));
            f = __half22float2(*(__half2*)&q.w); nsq = fmaf(f.x, f.x, fmaf(f.y, f.y, nsq));
        }
        nsq += __shfl_xor_sync(0xffffffffu, nsq, 1);
        nsq += __shfl_xor_sync(0xffffffffu, nsq, 2);
        if (seg == 0) s_an[cls] = sqrtf(nsq);
    }

    // ---- row norms from this warp's A slice: 2 lanes/row x 16 chunks = 32 ----
    {
        int lrow = lane >> 1, half = lane & 1;
        const char* agen = sm + wid * 8192 + lrow * 512;
        float nsq = 0.f;
        #pragma unroll
        for (int j = 0; j < 16; j++) {
            int chunk = half * 16 + j;
            uint4 q = *(const uint4*)(agen + ((chunk ^ (lrow & 7)) << 4));
            float2 f;
            f = __half22float2(*(__half2*)&q.x); nsq = fmaf(f.x, f.x, fmaf(f.y, f.y, nsq));
            f = __half22float2(*(__half2*)&q.y); nsq = fmaf(f.x, f.x, fmaf(f.y, f.y, nsq));
            f = __half22float2(*(__half2*)&q.z); nsq = fmaf(f.x, f.x, fmaf(f.y, f.y, nsq));
            f = __half22float2(*(__half2*)&q.w); nsq = fmaf(f.x, f.x, fmaf(f.y, f.y, nsq));
        }
        nsq += __shfl_xor_sync(0xffffffffu, nsq, 1);
        if (half == 0) s_rn[wid][lrow] = sqrtf(nsq);
    }
    __syncthreads();

    // ---- mma.sync m16n8k16: one m16 tile per warp, 2 n-tiles, 16 k-steps ----
    float c0[4] = {0,0,0,0}, c1[4] = {0,0,0,0};
    int sel   = lane >> 3;
    int lrow8 = lane & 7;
    int lrA = (sel & 1) * 8 + lrow8;     // local A row 0..15
    int cAadd = sel >> 1;
    int rB  = (sel >> 1) * 8 + lrow8;    // B row (class)
    int cBadd = sel & 1;
    uint32_t aab = sA + (uint32_t)(wid * 8192) + (uint32_t)(lrA * 512);
    uint32_t bab = sB + (uint32_t)(rB * 512);

    #pragma unroll
    for (int k = 0; k < 16; k++) {
        int cbase = 2 * k;
        uint32_t b0, b1, b2, b3;
        uint32_t baddr = bab + (uint32_t)(((cbase + cBadd) ^ (rB & 7)) << 4);
        asm volatile("ldmatrix.sync.aligned.m8n8.x4.shared.b16 {%0,%1,%2,%3}, [%4];"
                     : "=r"(b0), "=r"(b1), "=r"(b2), "=r"(b3) : "r"(baddr));
        uint32_t a0, a1, a2, a3;
        uint32_t aaddr = aab + (uint32_t)(((cbase + cAadd) ^ (lrA & 7)) << 4);
        asm volatile("ldmatrix.sync.aligned.m8n8.x4.shared.b16 {%0,%1,%2,%3}, [%4];"
                     : "=r"(a0), "=r"(a1), "=r"(a2), "=r"(a3) : "r"(aaddr));
        asm volatile("mma.sync.aligned.m16n8k16.row.col.f32.f16.f16.f32 "
                     "{%0,%1,%2,%3}, {%4,%5,%6,%7}, {%8,%9}, {%0,%1,%2,%3};"
                     : "+f"(c0[0]), "+f"(c0[1]), "+f"(c0[2]), "+f"(c0[3])
                     : "r"(a0), "r"(a1), "r"(a2), "r"(a3), "r"(b0), "r"(b1));
        asm volatile("mma.sync.aligned.m16n8k16.row.col.f32.f16.f16.f32 "
                     "{%0,%1,%2,%3}, {%4,%5,%6,%7}, {%8,%9}, {%0,%1,%2,%3};"
                     : "+f"(c1[0]), "+f"(c1[1]), "+f"(c1[2]), "+f"(c1[3])
                     : "r"(a0), "r"(a1), "r"(a2), "r"(a3), "r"(b2), "r"(b3));
    }

    // ---- epilogue: quad owns a row's 16 cols; cosine + softmax in registers ----
    int j2 = (lane & 3) * 2;
    float an0 = s_an[j2];
    float an1 = s_an[j2 + 1];
    float an2 = s_an[j2 + 8];
    float an3 = s_an[j2 + 9];

    #pragma unroll
    for (int h = 0; h < 2; h++) {
        int lr = (lane >> 2) + h * 8;
        int r = rowbase + lr;
        float rn = s_rn[wid][lr];
        float v0 = __fdividef(c0[2*h],   fmaxf(rn * an0, 1e-8f));
        float v1 = __fdividef(c0[2*h+1], fmaxf(rn * an1, 1e-8f));
        float v2 = __fdividef(c1[2*h],   fmaxf(rn * an2, 1e-8f));
        float v3 = __fdividef(c1[2*h+1], fmaxf(rn * an3, 1e-8f));
        float mx = fmaxf(fmaxf(v0, v1), fmaxf(v2, v3));
        mx = fmaxf(mx, __shfl_xor_sync(0xffffffffu, mx, 1));
        mx = fmaxf(mx, __shfl_xor_sync(0xffffffffu, mx, 2));
        v0 = __expf(v0 - mx); v1 = __expf(v1 - mx);
        v2 = __expf(v2 - mx); v3 = __expf(v3 - mx);
        float ssum = v0 + v1 + v2 + v3;
        ssum += __shfl_xor_sync(0xffffffffu, ssum, 1);
        ssum += __shfl_xor_sync(0xffffffffu, ssum, 2);
        float inv = 1.f / ssum;
        if (r < N) {
            float2* op = (float2*)(out + (size_t)r * NC);
            op[j2 >> 1]       = make_float2(v0 * inv, v1 * inv);
            op[(j2 >> 1) + 4] = make_float2(v2 * inv, v3 * inv);
        }
    }
}

// ---------------- launcher ----------------
extern "C" void kernel_launch(void* const* d_in, const int* in_sizes, int n_in,
                              void* d_out, int out_size) {
    const float* seq    = (const float*)d_in[0];
    const float* seq1   = (const float*)d_in[1];
    const int*   labels = (const int*)  d_in[2];
    const float* p1     = (const float*)d_in[3];
    const float* p2     = (const float*)d_in[4];
    const float* p3     = (const float*)d_in[5];
    const float* wwp    = (const float*)d_in[6];
    const float* wwf    = (const float*)d_in[7];
    const float* wdp    = (const float*)d_in[8];
    const float* a4     = (const float*)d_in[9];
    float* out = (float*)d_out;

    int N = in_sizes[0] / FT;
    if (N > NMAX) N = NMAX;
    int mtiles = (N + MTILE - 1) / MTILE;       // 1563

    int smem3 = 32768 + 8192;                   // 40KB
    cudaFuncSetAttribute(k_out, cudaFuncAttributeMaxDynamicSharedMemorySize, smem3);

    k_main<<<G2, 256>>>((const float2*)seq, (const float2*)seq1, labels,
                        (const float2*)p1, (const float2*)p2, (const float2*)p3,
                        wwp, wwf, (const float2*)wdp, a4, N);
    k_reduce<<<64, 512>>>();
    k_out<<<mtiles, 128, smem3>>>(out, N);
}